// round 1
// baseline (speedup 1.0000x reference)
#include <cuda_runtime.h>
#include <cstdint>

#define BATCHN 4
#define SEQ    2048
#define DM     1024
#define DI     2048
#define DS     64
#define TOKS   (BATCHN*SEQ)   // 8192

// ---------------- scratch (device globals; no allocations) ----------------
__device__ __align__(128) float g_xz[(size_t)TOKS * 2 * DI];   // 8192 x 4096
__device__ __align__(128) float g_xconv[(size_t)TOKS * DI];    // 8192 x 2048
__device__ __align__(128) float g_dt[(size_t)TOKS * DI];
__device__ __align__(128) float g_coef[(size_t)TOKS * DI];
__device__ __align__(128) float g_BC[(size_t)TOKS * 128];      // [B(64) | C(64)] per token
__device__ __align__(128) float g_s[TOKS];                     // raw dt logit per token
__device__ __align__(128) float g_y[(size_t)TOKS * DI];        // raw scan output
__device__ __align__(128) float g_ya[(size_t)TOKS * DI];       // gated activation
__device__ __align__(128) float g_Wxp[DI * 128];               // W_x[:, :128] packed
__device__ __align__(128) float g_wlast[DI];                   // W_x[:, 128]

// ---------------- generic fp32 SGEMM: 128x128 tile, BK=8, double buffered ----------------
// C[M,N] = A[M,K] @ B[K,N], all row-major, M%128==0, N%128==0, K%8==0
__global__ __launch_bounds__(256, 2)
void sgemm128x128(const float* __restrict__ A, const float* __restrict__ B,
                  float* __restrict__ C, int M, int N, int K) {
    __shared__ float As[2][8][128];
    __shared__ float Bs[2][8][128];
    const int tid = threadIdx.x;
    const int bm = blockIdx.y * 128;
    const int bn = blockIdx.x * 128;

    const int aRow = tid >> 1;          // 0..127
    const int aCol = (tid & 1) << 2;    // 0 or 4
    const int bRow = tid >> 5;          // 0..7
    const int bCol = (tid & 31) << 2;   // 0..124

    const float* Ap = A + (size_t)(bm + aRow) * K + aCol;
    const float* Bp = B + (size_t)bRow * N + (bn + bCol);

    const int tx = tid & 15;
    const int ty = tid >> 4;

    float acc[8][8];
#pragma unroll
    for (int i = 0; i < 8; i++)
#pragma unroll
        for (int j = 0; j < 8; j++) acc[i][j] = 0.f;

    // prologue: tile 0
    {
        float4 a4 = *(const float4*)Ap;
        float4 b4 = *(const float4*)Bp;
        As[0][aCol + 0][aRow] = a4.x;
        As[0][aCol + 1][aRow] = a4.y;
        As[0][aCol + 2][aRow] = a4.z;
        As[0][aCol + 3][aRow] = a4.w;
        *(float4*)&Bs[0][bRow][bCol] = b4;
    }
    __syncthreads();

    const int ntiles = K >> 3;
    int buf = 0;
    for (int t = 0; t < ntiles; ++t) {
        float4 na, nb;
        const bool more = (t + 1 < ntiles);
        if (more) {
            na = *(const float4*)(Ap + (size_t)(t + 1) * 8);
            nb = *(const float4*)(Bp + (size_t)(t + 1) * 8 * N);
        }
#pragma unroll
        for (int kk = 0; kk < 8; kk++) {
            float4 a0 = *(const float4*)&As[buf][kk][(ty << 2)];
            float4 a1 = *(const float4*)&As[buf][kk][64 + (ty << 2)];
            float4 b0 = *(const float4*)&Bs[buf][kk][(tx << 2)];
            float4 b1 = *(const float4*)&Bs[buf][kk][64 + (tx << 2)];
            float ar[8] = {a0.x, a0.y, a0.z, a0.w, a1.x, a1.y, a1.z, a1.w};
            float br[8] = {b0.x, b0.y, b0.z, b0.w, b1.x, b1.y, b1.z, b1.w};
#pragma unroll
            for (int i = 0; i < 8; i++)
#pragma unroll
                for (int j = 0; j < 8; j++)
                    acc[i][j] = fmaf(ar[i], br[j], acc[i][j]);
        }
        if (more) {
            const int ob = buf ^ 1;
            As[ob][aCol + 0][aRow] = na.x;
            As[ob][aCol + 1][aRow] = na.y;
            As[ob][aCol + 2][aRow] = na.z;
            As[ob][aCol + 3][aRow] = na.w;
            *(float4*)&Bs[ob][bRow][bCol] = nb;
        }
        __syncthreads();
        buf ^= 1;
    }

#pragma unroll
    for (int ig = 0; ig < 2; ig++) {
#pragma unroll
        for (int i = 0; i < 4; i++) {
            const int row = bm + ig * 64 + (ty << 2) + i;
            float* Cp = C + (size_t)row * N + bn;
            float4 v0 = make_float4(acc[ig * 4 + i][0], acc[ig * 4 + i][1],
                                    acc[ig * 4 + i][2], acc[ig * 4 + i][3]);
            float4 v1 = make_float4(acc[ig * 4 + i][4], acc[ig * 4 + i][5],
                                    acc[ig * 4 + i][6], acc[ig * 4 + i][7]);
            *(float4*)&Cp[(tx << 2)] = v0;
            *(float4*)&Cp[64 + (tx << 2)] = v1;
        }
    }
}

// ---------------- repack W_x (ld 129 -> aligned 128 + last column) ----------------
__global__ void pack_wx_kernel(const float* __restrict__ Wx) {
    const int k = blockIdx.x * blockDim.x + threadIdx.x;
    if (k >= DI) return;
    const float* src = Wx + (size_t)k * 129;
    float* dst = g_Wxp + (size_t)k * 128;
#pragma unroll 4
    for (int c = 0; c < 128; c++) dst[c] = src[c];
    g_wlast[k] = src[128];
}

// ---------------- depthwise causal conv (d_conv=4) + silu ----------------
__global__ void conv_silu_kernel(const float* __restrict__ cw, const float* __restrict__ cb) {
    const int d = blockIdx.x * blockDim.x + threadIdx.x;   // 0..2047
    const int t0 = blockIdx.y * 64;
    const int b = blockIdx.z;
    const float w0 = cw[d * 4 + 0], w1 = cw[d * 4 + 1];
    const float w2 = cw[d * 4 + 2], w3 = cw[d * 4 + 3];
    const float bias = cb[d];
    const float* xp = g_xz + (size_t)b * SEQ * (2 * DI) + d;   // x_ssm half
    float xm3 = (t0 >= 3) ? xp[(size_t)(t0 - 3) * (2 * DI)] : 0.f;
    float xm2 = (t0 >= 2) ? xp[(size_t)(t0 - 2) * (2 * DI)] : 0.f;
    float xm1 = (t0 >= 1) ? xp[(size_t)(t0 - 1) * (2 * DI)] : 0.f;
    const float* xq = xp + (size_t)t0 * (2 * DI);
    float* yp = g_xconv + ((size_t)b * SEQ + t0) * DI + d;
    for (int i = 0; i < 64; i++) {
        float x0 = xq[(size_t)i * (2 * DI)];
        float v = fmaf(w0, xm3, fmaf(w1, xm2, fmaf(w2, xm1, fmaf(w3, x0, bias))));
        yp[(size_t)i * DI] = v / (1.f + __expf(-v));
        xm3 = xm2; xm2 = xm1; xm1 = x0;
    }
}

// ---------------- last W_x column: s[tok] = x_conv[tok,:] . wlast ----------------
__global__ void lastcol_kernel() {
    const int lane = threadIdx.x & 31;
    const int tok = (blockIdx.x * blockDim.x + threadIdx.x) >> 5;
    const float* xp = g_xconv + (size_t)tok * DI;
    float acc = 0.f;
#pragma unroll 4
    for (int i = lane; i < DI; i += 32) acc = fmaf(xp[i], g_wlast[i], acc);
#pragma unroll
    for (int o = 16; o; o >>= 1) acc += __shfl_xor_sync(0xffffffffu, acc, o);
    if (!lane) g_s[tok] = acc;
}

// ---------------- dt = softplus(s + dt_bias), coef = dt * x_conv ----------------
__device__ __forceinline__ float softplusf(float v) {
    return (v > 20.f) ? v : log1pf(__expf(v));
}

__global__ void dtcoef_kernel(const float* __restrict__ dtb) {
    const size_t idx = ((size_t)blockIdx.x * blockDim.x + threadIdx.x) * 4;
    const int tok = (int)(idx >> 11);
    const int d = (int)(idx & 2047);
    const float sv = g_s[tok];
    float4 db = *(const float4*)&dtb[d];
    float4 x4 = *(const float4*)&g_xconv[idx];
    float4 dt4, cf4;
    dt4.x = softplusf(sv + db.x); cf4.x = dt4.x * x4.x;
    dt4.y = softplusf(sv + db.y); cf4.y = dt4.y * x4.y;
    dt4.z = softplusf(sv + db.z); cf4.z = dt4.z * x4.z;
    dt4.w = softplusf(sv + db.w); cf4.w = dt4.w * x4.w;
    *(float4*)&g_dt[idx] = dt4;
    *(float4*)&g_coef[idx] = cf4;
}

// ---------------- selective scan: 1 warp per (b,d), 2 states per lane ----------------
__global__ __launch_bounds__(256)
void scan_kernel(const float* __restrict__ A_log) {
    const int lane = threadIdx.x & 31;
    const int warp = threadIdx.x >> 5;
    const int d = blockIdx.x * 8 + warp;
    const int b = blockIdx.y;

    float2 al = *(const float2*)&A_log[(size_t)d * DS + lane * 2];
    const float a1 = -expf(al.x);
    const float a2 = -expf(al.y);

    float h1 = 0.f, h2 = 0.f;
    const float* dtp = g_dt + (size_t)b * SEQ * DI + d;
    const float* cfp = g_coef + (size_t)b * SEQ * DI + d;
    const float* bcp = g_BC + (size_t)b * SEQ * 128 + lane * 2;
    float* yp = g_y + (size_t)b * SEQ * DI + d;

    for (int t = 0; t < SEQ; t++) {
        const float dtv = __ldg(dtp);
        const float cf = __ldg(cfp);
        const float2 Bv = *(const float2*)bcp;
        const float2 Cv = *(const float2*)(bcp + 64);
        h1 = fmaf(__expf(a1 * dtv), h1, cf * Bv.x);
        h2 = fmaf(__expf(a2 * dtv), h2, cf * Bv.y);
        float yv = fmaf(h1, Cv.x, h2 * Cv.y);
#pragma unroll
        for (int o = 16; o; o >>= 1) yv += __shfl_xor_sync(0xffffffffu, yv, o);
        if (lane == 0) *yp = yv;
        dtp += DI; cfp += DI; bcp += 128; yp += DI;
    }
}

// ---------------- ya = (y + D*x_conv) * silu(z) ----------------
__global__ void epi_kernel(const float* __restrict__ Dv) {
    const size_t idx = ((size_t)blockIdx.x * blockDim.x + threadIdx.x) * 4;
    const int tok = (int)(idx >> 11);
    const int d = (int)(idx & 2047);
    float4 y4 = *(const float4*)&g_y[idx];
    float4 xc4 = *(const float4*)&g_xconv[idx];
    float4 z4 = *(const float4*)&g_xz[(size_t)tok * (2 * DI) + DI + d];
    float4 D4 = *(const float4*)&Dv[d];
    float4 o;
    o.x = fmaf(D4.x, xc4.x, y4.x) * (z4.x / (1.f + __expf(-z4.x)));
    o.y = fmaf(D4.y, xc4.y, y4.y) * (z4.y / (1.f + __expf(-z4.y)));
    o.z = fmaf(D4.z, xc4.z, y4.z) * (z4.z / (1.f + __expf(-z4.z)));
    o.w = fmaf(D4.w, xc4.w, y4.w) * (z4.w / (1.f + __expf(-z4.w)));
    *(float4*)&g_ya[idx] = o;
}

// ---------------- launch ----------------
extern "C" void kernel_launch(void* const* d_in, const int* in_sizes, int n_in,
                              void* d_out, int out_size) {
    const float* x       = (const float*)d_in[0];
    const float* W_in    = (const float*)d_in[1];
    const float* conv_w  = (const float*)d_in[2];
    const float* conv_b  = (const float*)d_in[3];
    const float* W_x     = (const float*)d_in[4];
    const float* A_log   = (const float*)d_in[5];
    const float* dt_bias = (const float*)d_in[6];
    const float* Dv      = (const float*)d_in[7];
    const float* W_out   = (const float*)d_in[8];
    float* out = (float*)d_out;
    (void)in_sizes; (void)n_in; (void)out_size;

    float *p_xz, *p_xconv, *p_BC, *p_Wxp, *p_ya;
    cudaGetSymbolAddress((void**)&p_xz, g_xz);
    cudaGetSymbolAddress((void**)&p_xconv, g_xconv);
    cudaGetSymbolAddress((void**)&p_BC, g_BC);
    cudaGetSymbolAddress((void**)&p_Wxp, g_Wxp);
    cudaGetSymbolAddress((void**)&p_ya, g_ya);

    // 0) repack W_x for aligned access
    pack_wx_kernel<<<(DI + 255) / 256, 256>>>(W_x);

    // 1) xz = x @ W_in   (8192 x 4096 x 1024)
    sgemm128x128<<<dim3((2 * DI) / 128, TOKS / 128), 256>>>(x, W_in, p_xz, TOKS, 2 * DI, DM);

    // 2) depthwise causal conv + silu -> x_conv
    conv_silu_kernel<<<dim3(DI / 256, SEQ / 64, BATCHN), 256>>>(conv_w, conv_b);

    // 3) [B|C] = x_conv @ W_x[:, :128]   (8192 x 128 x 2048)
    sgemm128x128<<<dim3(1, TOKS / 128), 256>>>(p_xconv, p_Wxp, p_BC, TOKS, 128, DI);

    // 3b) s = x_conv . W_x[:, 128]
    lastcol_kernel<<<TOKS / 8, 256>>>();

    // 4) dt / coef precompute
    dtcoef_kernel<<<((size_t)TOKS * DI / 4) / 256, 256>>>(dt_bias);

    // 5) selective scan
    scan_kernel<<<dim3(DI / 8, BATCHN), 256>>>(A_log);

    // 6) gated activation
    epi_kernel<<<((size_t)TOKS * DI / 4) / 256, 256>>>(Dv);

    // 7) out = ya @ W_out   (8192 x 1024 x 2048)
    sgemm128x128<<<dim3(DM / 128, TOKS / 128), 256>>>(p_ya, W_out, out, TOKS, DM, DI);
}

// round 5
// speedup vs baseline: 1.4421x; 1.4421x over previous
#include <cuda_runtime.h>
#include <cuda_bf16.h>
#include <cstdint>

#define BATCHN 4
#define SEQ    2048
#define DM     1024
#define DI     2048
#define DS     64
#define TOKS   (BATCHN*SEQ)   // 8192

typedef __nv_bfloat16 bf16;

// ---------------- scratch (device globals; no allocations) ----------------
__device__ __align__(128) float  g_xz[(size_t)TOKS * 2 * DI];
__device__ __align__(128) float  g_xconv[(size_t)TOKS * DI];
__device__ __align__(128) bf16   g_xc_hi[(size_t)TOKS * DI];
__device__ __align__(128) bf16   g_xc_lo[(size_t)TOKS * DI];
__device__ __align__(128) float2 g_dtcf[(size_t)TOKS * DI];   // (m=-log2e*dt, cf=dt*xconv)
__device__ __align__(128) float  g_BC[(size_t)TOKS * 128];
__device__ __align__(128) float  g_s[TOKS];
__device__ __align__(128) float  g_y[(size_t)TOKS * DI];
__device__ __align__(128) bf16   g_ya_hi[(size_t)TOKS * DI];
__device__ __align__(128) bf16   g_ya_lo[(size_t)TOKS * DI];
__device__ __align__(128) bf16   g_x_hi[(size_t)TOKS * DM];
__device__ __align__(128) bf16   g_x_lo[(size_t)TOKS * DM];
__device__ __align__(128) bf16   g_Wti_hi[(size_t)(2*DI) * DM];  // W_in^T  [4096][1024]
__device__ __align__(128) bf16   g_Wti_lo[(size_t)(2*DI) * DM];
__device__ __align__(128) bf16   g_Wto_hi[(size_t)DM * DI];      // W_out^T [1024][2048]
__device__ __align__(128) bf16   g_Wto_lo[(size_t)DM * DI];
__device__ __align__(128) bf16   g_Wxt_hi[128 * DI];             // W_x^T   [128][2048]
__device__ __align__(128) bf16   g_Wxt_lo[128 * DI];
__device__ __align__(128) float  g_wlast[DI];

// ---------------- helpers ----------------
__device__ __forceinline__ uint32_t s2u(const void* p) {
    uint32_t a;
    asm("{ .reg .u64 t; cvta.to.shared.u64 t, %1; cvt.u32.u64 %0, t; }" : "=r"(a) : "l"(p));
    return a;
}
__device__ __forceinline__ void split2(float v, bf16& h, bf16& l) {
    h = __float2bfloat16(v);
    l = __float2bfloat16(v - __bfloat162float(h));
}
__device__ __forceinline__ float ex2f(float x) {
    float r; asm("ex2.approx.f32 %0, %1;" : "=f"(r) : "f"(x)); return r;
}

#define CP16(sa, ga) \
    asm volatile("cp.async.cg.shared.global [%0], [%1], 16;" :: "r"(sa), "l"(ga))
#define LDSM4(r, a) \
    asm volatile("ldmatrix.sync.aligned.m8n8.x4.shared.b16 {%0,%1,%2,%3}, [%4];" \
                 : "=r"((r)[0]), "=r"((r)[1]), "=r"((r)[2]), "=r"((r)[3]) : "r"(a))
#define MMA(c, a, b0, b1)                                                        \
    asm volatile("mma.sync.aligned.m16n8k16.row.col.f32.bf16.bf16.f32 "          \
                 "{%0,%1,%2,%3}, {%4,%5,%6,%7}, {%8,%9}, {%0,%1,%2,%3};"         \
                 : "+f"((c)[0]), "+f"((c)[1]), "+f"((c)[2]), "+f"((c)[3])        \
                 : "r"((a)[0]), "r"((a)[1]), "r"((a)[2]), "r"((a)[3]),           \
                   "r"(b0), "r"(b1))

// ============================================================================
// bf16x3 HMMA GEMM: C[128x128 tile] = A[M,K] @ B[N,K]^T
// A,B given as (hi,lo) bf16 K-major. C fp32 row-major, ld=ldC.
// grid=(Ntot/128, M/128), 256 threads (8 warps, 2x4), warp tile 64x32.
// K-chunk 32, 3-stage cp.async pipeline.
// smem stage layout: [Ahi 8K][Alo 8K][Bhi 8K][Blo 8K], rows=64B, chunk swizzle.
// ============================================================================
#define NSTAGES 3
#define STAGEB  32768
#define GEMM_SMEM_DYN (NSTAGES * STAGEB)   // 96 KB

__global__ __launch_bounds__(256)
void mma_gemm(const bf16* __restrict__ Ahi, const bf16* __restrict__ Alo,
              const bf16* __restrict__ Bhi, const bf16* __restrict__ Blo,
              float* __restrict__ C, int K, int ldC) {
    extern __shared__ char sm[];
    const uint32_t sbase = s2u(sm);
    const int tid = threadIdx.x;
    const int lane = tid & 31;
    const int wid = tid >> 5;
    const int warpM = wid & 1;       // 0..1  -> 64 rows each
    const int warpN = wid >> 1;      // 0..3  -> 32 cols each
    const int bm = blockIdx.y * 128;
    const int bn = blockIdx.x * 128;

    // ---- load geometry: thread -> (row = tid>>1, chunks c0,c0+1), 16B each
    const int lrow = tid >> 1;
    const int lc0 = (tid & 1) * 2;
    const uint32_t lsw = (uint32_t)((lrow >> 1) & 3);
    const uint32_t so0 = (uint32_t)lrow * 64 + (((uint32_t)lc0 ^ lsw) << 4);
    const uint32_t so1 = (uint32_t)lrow * 64 + ((((uint32_t)lc0 + 1u) ^ lsw) << 4);
    const bf16* pAh = Ahi + (size_t)(bm + lrow) * K + lc0 * 8;
    const bf16* pAl = Alo + (size_t)(bm + lrow) * K + lc0 * 8;
    const bf16* pBh = Bhi + (size_t)(bn + lrow) * K + lc0 * 8;
    const bf16* pBl = Blo + (size_t)(bn + lrow) * K + lc0 * 8;

#define ISSUE(st, kc) do {                                                   \
    const uint32_t b_ = sbase + (uint32_t)(st) * STAGEB;                     \
    const size_t ko_ = (size_t)(kc) * 32;                                    \
    CP16(b_ + so0,          pAh + ko_);  CP16(b_ + so1,          pAh + ko_ + 8); \
    CP16(b_ + 8192 + so0,   pAl + ko_);  CP16(b_ + 8192 + so1,   pAl + ko_ + 8); \
    CP16(b_ + 16384 + so0,  pBh + ko_);  CP16(b_ + 16384 + so1,  pBh + ko_ + 8); \
    CP16(b_ + 24576 + so0,  pBl + ko_);  CP16(b_ + 24576 + so1,  pBl + ko_ + 8); \
} while (0)

    float acc[4][4][4];
#pragma unroll
    for (int i = 0; i < 4; i++)
#pragma unroll
        for (int j = 0; j < 4; j++)
#pragma unroll
            for (int k = 0; k < 4; k++) acc[i][j][k] = 0.f;

    const int NC = K >> 5;
#pragma unroll 1
    for (int s = 0; s < NSTAGES - 1; s++) {
        ISSUE(s, s);
        asm volatile("cp.async.commit_group;" ::: "memory");
    }

    // ldmatrix lane geometry (constant across tiles/steps)
    const uint32_t fsw = (uint32_t)(((lane & 15) >> 1) & 3);
    const uint32_t frow = (uint32_t)(lane & 15);
    const uint32_t fk = (uint32_t)(lane >> 4);   // 0/1 -> +8 k

#pragma unroll 1
    for (int c = 0; c < NC; c++) {
        asm volatile("cp.async.wait_group %0;" :: "n"(NSTAGES - 2));
        __syncthreads();
        const int nk = c + NSTAGES - 1;
        if (nk < NC) ISSUE(nk % NSTAGES, nk);
        asm volatile("cp.async.commit_group;" ::: "memory");

        const uint32_t bb = sbase + (uint32_t)(c % NSTAGES) * STAGEB;
#pragma unroll
        for (int s = 0; s < 2; s++) {
            const uint32_t ch = (((uint32_t)(s * 2) + fk) ^ fsw) << 4;
            uint32_t Ah[4][4], Al[4][4], Bh[2][4], Bl[2][4];
#pragma unroll
            for (int i = 0; i < 4; i++) {
                const uint32_t ro = (uint32_t)(warpM * 64 + i * 16 + frow) * 64;
                LDSM4(Ah[i], bb + ro + ch);
                LDSM4(Al[i], bb + 8192 + ro + ch);
            }
#pragma unroll
            for (int g = 0; g < 2; g++) {
                const uint32_t ro = (uint32_t)(warpN * 32 + g * 16 + frow) * 64;
                LDSM4(Bh[g], bb + 16384 + ro + ch);
                LDSM4(Bl[g], bb + 24576 + ro + ch);
            }
#pragma unroll
            for (int i = 0; i < 4; i++)
#pragma unroll
                for (int g = 0; g < 2; g++)
#pragma unroll
                    for (int h = 0; h < 2; h++) {
                        float* cc = acc[i][g * 2 + h];
                        MMA(cc, Ah[i], Bh[g][h], Bh[g][h + 2]);
                        MMA(cc, Ah[i], Bl[g][h], Bl[g][h + 2]);
                        MMA(cc, Al[i], Bh[g][h], Bh[g][h + 2]);
                    }
        }
        __syncthreads();
    }

    // epilogue: fragment -> float2 stores
#pragma unroll
    for (int i = 0; i < 4; i++) {
        const int r0 = bm + warpM * 64 + i * 16 + (lane >> 2);
#pragma unroll
        for (int j = 0; j < 4; j++) {
            const int cc = bn + warpN * 32 + j * 8 + (lane & 3) * 2;
            *(float2*)&C[(size_t)r0 * ldC + cc] = make_float2(acc[i][j][0], acc[i][j][1]);
            *(float2*)&C[(size_t)(r0 + 8) * ldC + cc] = make_float2(acc[i][j][2], acc[i][j][3]);
        }
    }
#undef ISSUE
}

// ---------------- prep kernels ----------------
__global__ void split_x_kernel(const float* __restrict__ x) {
    const size_t i = ((size_t)blockIdx.x * blockDim.x + threadIdx.x) * 4;
    float4 v = *(const float4*)&x[i];
    bf16 h0, h1, h2, h3, l0, l1, l2, l3;
    split2(v.x, h0, l0); split2(v.y, h1, l1); split2(v.z, h2, l2); split2(v.w, h3, l3);
    __nv_bfloat162 ha = __halves2bfloat162(h0, h1), hb = __halves2bfloat162(h2, h3);
    __nv_bfloat162 la = __halves2bfloat162(l0, l1), lb = __halves2bfloat162(l2, l3);
    uint2 uh, ul;
    uh.x = *(uint32_t*)&ha; uh.y = *(uint32_t*)&hb;
    ul.x = *(uint32_t*)&la; ul.y = *(uint32_t*)&lb;
    *(uint2*)&g_x_hi[i] = uh;
    *(uint2*)&g_x_lo[i] = ul;
}

__global__ void tsplit_kernel(const float* __restrict__ S, bf16* __restrict__ Dhi,
                              bf16* __restrict__ Dlo, int K, int N) {
    __shared__ float t[32][33];
    const int n0 = blockIdx.x * 32, k0 = blockIdx.y * 32;
    for (int j = threadIdx.y; j < 32; j += 8)
        t[j][threadIdx.x] = S[(size_t)(k0 + j) * N + n0 + threadIdx.x];
    __syncthreads();
    for (int j = threadIdx.y; j < 32; j += 8) {
        float v = t[threadIdx.x][j];
        bf16 h, l; split2(v, h, l);
        Dhi[(size_t)(n0 + j) * K + k0 + threadIdx.x] = h;
        Dlo[(size_t)(n0 + j) * K + k0 + threadIdx.x] = l;
    }
}

__global__ void pack_wx_kernel(const float* __restrict__ Wx) {
    const int idx = blockIdx.x * 256 + threadIdx.x;   // over 2048*128
    const int n = idx & 127, k = idx >> 7;
    const float v = Wx[(size_t)k * 129 + n];
    bf16 h, l; split2(v, h, l);
    g_Wxt_hi[(size_t)n * DI + k] = h;
    g_Wxt_lo[(size_t)n * DI + k] = l;
    if (n == 0) g_wlast[k] = Wx[(size_t)k * 129 + 128];
}

// ---------------- depthwise causal conv (d_conv=4) + silu + hi/lo ----------------
__global__ void conv_silu_kernel(const float* __restrict__ cw, const float* __restrict__ cb) {
    const int d = blockIdx.x * blockDim.x + threadIdx.x;
    const int t0 = blockIdx.y * 64;
    const int b = blockIdx.z;
    const float w0 = cw[d * 4 + 0], w1 = cw[d * 4 + 1];
    const float w2 = cw[d * 4 + 2], w3 = cw[d * 4 + 3];
    const float bias = cb[d];
    const float* xp = g_xz + (size_t)b * SEQ * (2 * DI) + d;
    float xm3 = (t0 >= 3) ? xp[(size_t)(t0 - 3) * (2 * DI)] : 0.f;
    float xm2 = (t0 >= 2) ? xp[(size_t)(t0 - 2) * (2 * DI)] : 0.f;
    float xm1 = (t0 >= 1) ? xp[(size_t)(t0 - 1) * (2 * DI)] : 0.f;
    const float* xq = xp + (size_t)t0 * (2 * DI);
    const size_t ob = ((size_t)b * SEQ + t0) * DI + d;
    for (int i = 0; i < 64; i++) {
        float x0 = xq[(size_t)i * (2 * DI)];
        float v = fmaf(w0, xm3, fmaf(w1, xm2, fmaf(w2, xm1, fmaf(w3, x0, bias))));
        float sv = v / (1.f + __expf(-v));
        const size_t o = ob + (size_t)i * DI;
        g_xconv[o] = sv;
        bf16 h, l; split2(sv, h, l);
        g_xc_hi[o] = h; g_xc_lo[o] = l;
        xm3 = xm2; xm2 = xm1; xm1 = x0;
    }
}

// ---------------- s[tok] = x_conv[tok,:] . wlast ----------------
__global__ void lastcol_kernel() {
    const int lane = threadIdx.x & 31;
    const int tok = (blockIdx.x * blockDim.x + threadIdx.x) >> 5;
    const float* xp = g_xconv + (size_t)tok * DI;
    float acc = 0.f;
#pragma unroll 4
    for (int i = lane; i < DI; i += 32) acc = fmaf(xp[i], g_wlast[i], acc);
#pragma unroll
    for (int o = 16; o; o >>= 1) acc += __shfl_xor_sync(0xffffffffu, acc, o);
    if (!lane) g_s[tok] = acc;
}

// ---------------- dt/coef ----------------
__device__ __forceinline__ float softplusf(float v) {
    return (v > 20.f) ? v : log1pf(__expf(v));
}
__global__ void dtcoef_kernel(const float* __restrict__ dtb) {
    const size_t idx = ((size_t)blockIdx.x * blockDim.x + threadIdx.x) * 4;
    const int tok = (int)(idx >> 11);
    const int d = (int)(idx & 2047);
    const float sv = g_s[tok];
    float4 db = *(const float4*)&dtb[d];
    float4 x4 = *(const float4*)&g_xconv[idx];
    const float NL2E = -1.4426950408889634f;
    float d0 = softplusf(sv + db.x), d1 = softplusf(sv + db.y);
    float d2 = softplusf(sv + db.z), d3 = softplusf(sv + db.w);
    *(float4*)&g_dtcf[idx]     = make_float4(d0 * NL2E, d0 * x4.x, d1 * NL2E, d1 * x4.y);
    *(float4*)&g_dtcf[idx + 2] = make_float4(d2 * NL2E, d2 * x4.z, d3 * NL2E, d3 * x4.w);
}

// ---------------- selective scan: 1 warp per (b,d), 2 states/lane ----------------
__global__ __launch_bounds__(256)
void scan_kernel(const float* __restrict__ A_log) {
    const int lane = threadIdx.x & 31;
    const int warp = threadIdx.x >> 5;
    const int d = blockIdx.x * 8 + warp;
    const int b = blockIdx.y;

    float2 al = *(const float2*)&A_log[(size_t)d * DS + lane * 2];
    const float e1 = __expf(al.x);   // = -a1 (positive)
    const float e2 = __expf(al.y);

    float h1 = 0.f, h2 = 0.f;
    const float2* dc = g_dtcf + (size_t)b * SEQ * DI + d;
    const float* bcp = g_BC + (size_t)b * SEQ * 128 + lane * 2;
    float* yp = g_y + (size_t)b * SEQ * DI + d;

#pragma unroll 4
    for (int t = 0; t < SEQ; t++) {
        const float2 mc = __ldg(dc);                 // broadcast (m, cf)
        const float2 Bv = *(const float2*)bcp;
        const float2 Cv = *(const float2*)(bcp + 64);
        h1 = fmaf(ex2f(mc.x * e1), h1, mc.y * Bv.x); // exp(a1*dt) = 2^(m*e1)
        h2 = fmaf(ex2f(mc.x * e2), h2, mc.y * Bv.y);
        float yv = fmaf(h1, Cv.x, h2 * Cv.y);
#pragma unroll
        for (int o = 16; o; o >>= 1) yv += __shfl_xor_sync(0xffffffffu, yv, o);
        if (lane == 0) *yp = yv;
        dc += DI; bcp += 128; yp += DI;
    }
}

// ---------------- ya = (y + D*x_conv) * silu(z) -> bf16 hi/lo ----------------
__global__ void epi_kernel(const float* __restrict__ Dv) {
    const size_t idx = ((size_t)blockIdx.x * blockDim.x + threadIdx.x) * 4;
    const int tok = (int)(idx >> 11);
    const int d = (int)(idx & 2047);
    float4 y4 = *(const float4*)&g_y[idx];
    float4 xc4 = *(const float4*)&g_xconv[idx];
    float4 z4 = *(const float4*)&g_xz[(size_t)tok * (2 * DI) + DI + d];
    float4 D4 = *(const float4*)&Dv[d];
    float o0 = fmaf(D4.x, xc4.x, y4.x) * (z4.x / (1.f + __expf(-z4.x)));
    float o1 = fmaf(D4.y, xc4.y, y4.y) * (z4.y / (1.f + __expf(-z4.y)));
    float o2 = fmaf(D4.z, xc4.z, y4.z) * (z4.z / (1.f + __expf(-z4.z)));
    float o3 = fmaf(D4.w, xc4.w, y4.w) * (z4.w / (1.f + __expf(-z4.w)));
    bf16 h0, h1, h2, h3, l0, l1, l2, l3;
    split2(o0, h0, l0); split2(o1, h1, l1); split2(o2, h2, l2); split2(o3, h3, l3);
    __nv_bfloat162 ha = __halves2bfloat162(h0, h1), hb = __halves2bfloat162(h2, h3);
    __nv_bfloat162 la = __halves2bfloat162(l0, l1), lb = __halves2bfloat162(l2, l3);
    uint2 uh, ul;
    uh.x = *(uint32_t*)&ha; uh.y = *(uint32_t*)&hb;
    ul.x = *(uint32_t*)&la; ul.y = *(uint32_t*)&lb;
    *(uint2*)&g_ya_hi[idx] = uh;
    *(uint2*)&g_ya_lo[idx] = ul;
}

// ---------------- launch ----------------
extern "C" void kernel_launch(void* const* d_in, const int* in_sizes, int n_in,
                              void* d_out, int out_size) {
    const float* x       = (const float*)d_in[0];
    const float* W_in    = (const float*)d_in[1];
    const float* conv_w  = (const float*)d_in[2];
    const float* conv_b  = (const float*)d_in[3];
    const float* W_x     = (const float*)d_in[4];
    const float* A_log   = (const float*)d_in[5];
    const float* dt_bias = (const float*)d_in[6];
    const float* Dv      = (const float*)d_in[7];
    const float* W_out   = (const float*)d_in[8];
    float* out = (float*)d_out;
    (void)in_sizes; (void)n_in; (void)out_size;

    cudaFuncSetAttribute(mma_gemm, cudaFuncAttributeMaxDynamicSharedMemorySize,
                         GEMM_SMEM_DYN);

    bf16 *xh, *xl, *wih, *wil, *woh, *wol, *wxh, *wxl, *xch, *xcl, *yah, *yal;
    float *p_xz, *p_BC;
    cudaGetSymbolAddress((void**)&xh, g_x_hi);   cudaGetSymbolAddress((void**)&xl, g_x_lo);
    cudaGetSymbolAddress((void**)&wih, g_Wti_hi); cudaGetSymbolAddress((void**)&wil, g_Wti_lo);
    cudaGetSymbolAddress((void**)&woh, g_Wto_hi); cudaGetSymbolAddress((void**)&wol, g_Wto_lo);
    cudaGetSymbolAddress((void**)&wxh, g_Wxt_hi); cudaGetSymbolAddress((void**)&wxl, g_Wxt_lo);
    cudaGetSymbolAddress((void**)&xch, g_xc_hi);  cudaGetSymbolAddress((void**)&xcl, g_xc_lo);
    cudaGetSymbolAddress((void**)&yah, g_ya_hi);  cudaGetSymbolAddress((void**)&yal, g_ya_lo);
    cudaGetSymbolAddress((void**)&p_xz, g_xz);
    cudaGetSymbolAddress((void**)&p_BC, g_BC);

    // prep: splits / transposes
    split_x_kernel<<<((size_t)TOKS * DM / 4) / 256, 256>>>(x);
    tsplit_kernel<<<dim3((2 * DI) / 32, DM / 32), dim3(32, 8)>>>(W_in, wih, wil, DM, 2 * DI);
    tsplit_kernel<<<dim3(DM / 32, DI / 32), dim3(32, 8)>>>(W_out, woh, wol, DI, DM);
    pack_wx_kernel<<<(DI * 128) / 256, 256>>>(W_x);

    // 1) xz = x @ W_in   (8192 x 4096 x 1024)
    mma_gemm<<<dim3((2 * DI) / 128, TOKS / 128), 256, GEMM_SMEM_DYN>>>(
        xh, xl, wih, wil, p_xz, DM, 2 * DI);

    // 2) conv + silu
    conv_silu_kernel<<<dim3(DI / 256, SEQ / 64, BATCHN), 256>>>(conv_w, conv_b);

    // 3) [B|C] = x_conv @ W_x[:, :128]   (8192 x 128 x 2048)
    mma_gemm<<<dim3(1, TOKS / 128), 256, GEMM_SMEM_DYN>>>(
        xch, xcl, wxh, wxl, p_BC, DI, 128);

    // 3b) dt logit
    lastcol_kernel<<<TOKS / 8, 256>>>();

    // 4) dt / coef
    dtcoef_kernel<<<((size_t)TOKS * DI / 4) / 256, 256>>>(dt_bias);

    // 5) scan
    scan_kernel<<<dim3(DI / 8, BATCHN), 256>>>(A_log);

    // 6) gated activation
    epi_kernel<<<((size_t)TOKS * DI / 4) / 256, 256>>>(Dv);

    // 7) out = ya @ W_out   (8192 x 1024 x 2048)
    mma_gemm<<<dim3(DM / 128, TOKS / 128), 256, GEMM_SMEM_DYN>>>(
        yah, yal, woh, wol, out, DI, DM);
}